// round 1
// baseline (speedup 1.0000x reference)
#include <cuda_runtime.h>
#include <math.h>

// ---------------- problem constants ----------------
#define NB    2
#define SEQ   2048
#define NTOK  (NB*SEQ)          // 4096 tokens
#define DIN   512
#define NH    8
#define DH    64
#define QOFF  0
#define KOFF  512               // D_Q
#define VOFF  1024              // D_Q + D_K
#define QKVN  5120              // 512+512+4096
#define DVH   512               // per-head value dim (= D_IN)
#define DEXP  2048

// ---------------- scratch (device globals; no allocations allowed) ----------
__device__ float g_xn [NTOK * (long)DIN];            //   8 MB
__device__ float g_qkv[NTOK * (long)QKVN];           //  80 MB
__device__ float g_S  [(long)NB*NH*SEQ*SEQ];         // 256 MB
__device__ float g_ao [NTOK * (long)(NH*DVH)];       //  64 MB
__device__ float g_x2 [NTOK * (long)DIN];            //   8 MB
__device__ float g_x2n[NTOK * (long)DIN];            //   8 MB
__device__ float g_h  [NTOK * (long)DEXP];           //  32 MB

// ---------------- LayerNorm: one block per row of 512 ----------------------
__global__ void ln_kernel(const float* __restrict__ x, const float* __restrict__ g,
                          const float* __restrict__ bta, float* __restrict__ o) {
    __shared__ float red[2][4];
    long row = blockIdx.x;
    const float* xr = x + row * DIN;
    float* orow = o + row * DIN;
    int t = threadIdx.x;                       // 128 threads * 4 elems
    float4 v = ((const float4*)xr)[t];
    float s  = v.x + v.y + v.z + v.w;
    float ss = v.x*v.x + v.y*v.y + v.z*v.z + v.w*v.w;
    #pragma unroll
    for (int off = 16; off > 0; off >>= 1) {
        s  += __shfl_down_sync(0xffffffffu, s,  off);
        ss += __shfl_down_sync(0xffffffffu, ss, off);
    }
    int warp = t >> 5, lane = t & 31;
    if (lane == 0) { red[0][warp] = s; red[1][warp] = ss; }
    __syncthreads();
    if (t == 0) {
        float S0 = red[0][0] + red[0][1] + red[0][2] + red[0][3];
        float S1 = red[1][0] + red[1][1] + red[1][2] + red[1][3];
        float mu  = S0 * (1.0f/DIN);
        float var = S1 * (1.0f/DIN) - mu*mu;
        red[0][0] = mu;
        red[1][0] = rsqrtf(var + 1e-5f);
    }
    __syncthreads();
    float mu = red[0][0], inv = red[1][0];
    float4 gg = ((const float4*)g)[t];
    float4 bb = ((const float4*)bta)[t];
    float4 r;
    r.x = (v.x - mu) * inv * gg.x + bb.x;
    r.y = (v.y - mu) * inv * gg.y + bb.y;
    r.z = (v.z - mu) * inv * gg.z + bb.z;
    r.w = (v.w - mu) * inv * gg.w + bb.w;
    ((float4*)orow)[t] = r;
}

// ---------------- row softmax over 2048 (one block of 256 per row) ---------
__global__ void softmax_kernel(float* __restrict__ S) {
    __shared__ float red[8];
    long row = blockIdx.x;
    float* r = S + row * (long)SEQ;
    int t = threadIdx.x;
    float4 a = ((float4*)r)[t];
    float4 b = ((float4*)r)[t + 256];
    float m = fmaxf(fmaxf(fmaxf(a.x,a.y),fmaxf(a.z,a.w)),
                    fmaxf(fmaxf(b.x,b.y),fmaxf(b.z,b.w)));
    #pragma unroll
    for (int off = 16; off > 0; off >>= 1)
        m = fmaxf(m, __shfl_xor_sync(0xffffffffu, m, off));
    int warp = t >> 5, lane = t & 31;
    if (lane == 0) red[warp] = m;
    __syncthreads();
    m = red[0];
    #pragma unroll
    for (int i = 1; i < 8; i++) m = fmaxf(m, red[i]);
    a.x = __expf(a.x - m); a.y = __expf(a.y - m); a.z = __expf(a.z - m); a.w = __expf(a.w - m);
    b.x = __expf(b.x - m); b.y = __expf(b.y - m); b.z = __expf(b.z - m); b.w = __expf(b.w - m);
    float s = a.x+a.y+a.z+a.w + b.x+b.y+b.z+b.w;
    #pragma unroll
    for (int off = 16; off > 0; off >>= 1)
        s += __shfl_xor_sync(0xffffffffu, s, off);
    __syncthreads();
    if (lane == 0) red[warp] = s;
    __syncthreads();
    s = red[0];
    #pragma unroll
    for (int i = 1; i < 8; i++) s += red[i];
    float inv = 1.0f / s;
    a.x *= inv; a.y *= inv; a.z *= inv; a.w *= inv;
    b.x *= inv; b.y *= inv; b.z *= inv; b.w *= inv;
    ((float4*)r)[t]       = a;
    ((float4*)r)[t + 256] = b;
}

// ---------------- generic tiled SGEMM: C = alpha*A@B(^T) [+bias][+res][swish]
// 128x128 tile, BK=8, 256 threads, 8x8 per thread. M,N % 128 == 0, K % 8 == 0.
// Batched via blockIdx.z: z1 = z/zdiv, z2 = z%zdiv; per-operand (s1,s2) offsets.
template<bool TRANSB, bool BIAS, bool RES, bool SWISH>
__global__ __launch_bounds__(256, 2)
void sgemm_kernel(const float* __restrict__ A, const float* __restrict__ B,
                  float* __restrict__ C, const float* __restrict__ bias,
                  const float* __restrict__ res,
                  int K, int lda, int ldb, int ldc,
                  long sA1, long sA2, long sB1, long sB2,
                  long sC1, long sC2, int zdiv, float alpha)
{
    int z  = blockIdx.z;
    int z1 = z / zdiv, z2 = z - z1 * zdiv;
    A += z1 * sA1 + (long)z2 * sA2;
    B += z1 * sB1 + (long)z2 * sB2;
    C += z1 * sC1 + (long)z2 * sC2;

    __shared__ float As[8][128];
    __shared__ float Bs[8][128];

    const int tid = threadIdx.x;
    const int tx  = tid & 15;
    const int ty  = tid >> 4;
    const long bm0 = (long)blockIdx.y * 128;
    const long bn0 = (long)blockIdx.x * 128;

    const int lrow = tid >> 1;
    const int lcol = (tid & 1) << 2;

    const float* Ap = A + (bm0 + lrow) * (long)lda + lcol;
    const float* Bp;
    if (TRANSB) Bp = B + (bn0 + lrow) * (long)ldb + lcol;
    else        Bp = B + (long)(tid >> 5) * ldb + bn0 + ((tid & 31) << 2);

    float acc[8][8];
    #pragma unroll
    for (int i = 0; i < 8; i++)
        #pragma unroll
        for (int j = 0; j < 8; j++) acc[i][j] = 0.0f;

    for (int k0 = 0; k0 < K; k0 += 8) {
        float4 av = *(const float4*)(Ap + k0);
        float4 bv;
        if (TRANSB) bv = *(const float4*)(Bp + k0);
        else        bv = *(const float4*)(Bp + (long)k0 * ldb);

        As[lcol+0][lrow] = av.x; As[lcol+1][lrow] = av.y;
        As[lcol+2][lrow] = av.z; As[lcol+3][lrow] = av.w;
        if (TRANSB) {
            Bs[lcol+0][lrow] = bv.x; Bs[lcol+1][lrow] = bv.y;
            Bs[lcol+2][lrow] = bv.z; Bs[lcol+3][lrow] = bv.w;
        } else {
            *(float4*)&Bs[tid >> 5][(tid & 31) << 2] = bv;
        }
        __syncthreads();

        #pragma unroll
        for (int kk = 0; kk < 8; kk++) {
            float a[8], b[8];
            *(float4*)(a)     = *(const float4*)&As[kk][ty*8];
            *(float4*)(a + 4) = *(const float4*)&As[kk][ty*8 + 4];
            *(float4*)(b)     = *(const float4*)&Bs[kk][tx*8];
            *(float4*)(b + 4) = *(const float4*)&Bs[kk][tx*8 + 4];
            #pragma unroll
            for (int i = 0; i < 8; i++)
                #pragma unroll
                for (int j = 0; j < 8; j++)
                    acc[i][j] += a[i] * b[j];
        }
        __syncthreads();
    }

    #pragma unroll
    for (int i = 0; i < 8; i++) {
        long r = bm0 + ty*8 + i;
        #pragma unroll
        for (int j = 0; j < 8; j += 4) {
            long c = bn0 + tx*8 + j;
            float4 v;
            v.x = acc[i][j]   * alpha; v.y = acc[i][j+1] * alpha;
            v.z = acc[i][j+2] * alpha; v.w = acc[i][j+3] * alpha;
            if (BIAS) {
                float4 bb = *(const float4*)(bias + c);
                v.x += bb.x; v.y += bb.y; v.z += bb.z; v.w += bb.w;
            }
            if (SWISH) {
                v.x = v.x / (1.0f + __expf(-v.x));
                v.y = v.y / (1.0f + __expf(-v.y));
                v.z = v.z / (1.0f + __expf(-v.z));
                v.w = v.w / (1.0f + __expf(-v.w));
            }
            if (RES) {
                float4 rr = *(const float4*)(res + r * (long)ldc + c);
                v.x += rr.x; v.y += rr.y; v.z += rr.z; v.w += rr.w;
            }
            *(float4*)(C + r * (long)ldc + c) = v;
        }
    }
}

// ---------------- host orchestration ----------------
extern "C" void kernel_launch(void* const* d_in, const int* in_sizes, int n_in,
                              void* d_out, int out_size) {
    const float* x     = (const float*)d_in[0];
    const float* ln1_g = (const float*)d_in[1];
    const float* ln1_b = (const float*)d_in[2];
    const float* Wqkv  = (const float*)d_in[3];
    const float* bqkv  = (const float*)d_in[4];
    const float* Wm    = (const float*)d_in[5];
    const float* bm    = (const float*)d_in[6];
    const float* ln2_g = (const float*)d_in[7];
    const float* ln2_b = (const float*)d_in[8];
    const float* W1    = (const float*)d_in[9];
    const float* b1    = (const float*)d_in[10];
    const float* W2    = (const float*)d_in[11];
    const float* b2    = (const float*)d_in[12];
    float* out = (float*)d_out;

    float *xn, *qkv, *S, *ao, *x2, *x2n, *h;
    cudaGetSymbolAddress((void**)&xn,  g_xn);
    cudaGetSymbolAddress((void**)&qkv, g_qkv);
    cudaGetSymbolAddress((void**)&S,   g_S);
    cudaGetSymbolAddress((void**)&ao,  g_ao);
    cudaGetSymbolAddress((void**)&x2,  g_x2);
    cudaGetSymbolAddress((void**)&x2n, g_x2n);
    cudaGetSymbolAddress((void**)&h,   g_h);

    const float scale = 0.125f;  // 1/sqrt(64)

    // 1) LN1
    ln_kernel<<<NTOK, 128>>>(x, ln1_g, ln1_b, xn);

    // 2) qkv = xn @ Wqkv + bqkv            (4096 x 5120, K=512)
    sgemm_kernel<false, true, false, false><<<dim3(QKVN/128, NTOK/128, 1), 256>>>(
        xn, Wqkv, qkv, bqkv, nullptr,
        DIN, DIN, QKVN, QKVN,
        0, 0, 0, 0, 0, 0, 1, 1.0f);

    // 3) S[b,h] = scale * Q[b,h] @ K[b,h]^T   (2048 x 2048, K=64), 16 batches
    sgemm_kernel<true, false, false, false><<<dim3(SEQ/128, SEQ/128, NB*NH), 256>>>(
        qkv + QOFF, qkv + KOFF, S, nullptr, nullptr,
        DH, QKVN, QKVN, SEQ,
        (long)SEQ*QKVN, DH,                 // A: per-b, per-h
        (long)SEQ*QKVN, DH,                 // B: per-b, per-h
        (long)NH*SEQ*SEQ, (long)SEQ*SEQ,    // C: per-b, per-h
        NH, scale);

    // 4) softmax rows of S
    softmax_kernel<<<NB*NH*SEQ, 256>>>(S);

    // 5) ao[b,n,h*512+c] = P[b,h] @ V[b,h]    (2048 x 512, K=2048), 16 batches
    sgemm_kernel<false, false, false, false><<<dim3(DVH/128, SEQ/128, NB*NH), 256>>>(
        S, qkv + VOFF, ao, nullptr, nullptr,
        SEQ, SEQ, QKVN, NH*DVH,
        (long)NH*SEQ*SEQ, (long)SEQ*SEQ,    // A: per-b, per-h
        (long)SEQ*QKVN, DVH,                // B: per-b, per-h
        (long)SEQ*NH*DVH, DVH,              // C: per-b, per-h
        NH, 1.0f);

    // 6) x2 = ao @ Wm + bm + x              (4096 x 512, K=4096)
    sgemm_kernel<false, true, true, false><<<dim3(DIN/128, NTOK/128, 1), 256>>>(
        ao, Wm, x2, bm, x,
        NH*DVH, NH*DVH, DIN, DIN,
        0, 0, 0, 0, 0, 0, 1, 1.0f);

    // 7) LN2
    ln_kernel<<<NTOK, 128>>>(x2, ln2_g, ln2_b, x2n);

    // 8) h = swish(x2n @ W1 + b1)           (4096 x 2048, K=512)
    sgemm_kernel<false, true, false, true><<<dim3(DEXP/128, NTOK/128, 1), 256>>>(
        x2n, W1, h, b1, nullptr,
        DIN, DIN, DEXP, DEXP,
        0, 0, 0, 0, 0, 0, 1, 1.0f);

    // 9) out = h @ W2 + b2 + x2             (4096 x 512, K=2048)
    sgemm_kernel<false, true, true, false><<<dim3(DIN/128, NTOK/128, 1), 256>>>(
        h, W2, out, b2, x2,
        DEXP, DEXP, DIN, DIN,
        0, 0, 0, 0, 0, 0, 1, 1.0f);
}

// round 3
// speedup vs baseline: 2.3806x; 2.3806x over previous
#include <cuda_runtime.h>
#include <cuda_bf16.h>
#include <cstdint>
#include <math.h>

// ---------------- problem constants ----------------
#define NB    2
#define SEQ   2048
#define NTOK  (NB*SEQ)          // 4096 tokens
#define DIN   512
#define NH    8
#define DH    64
#define QOFF  0
#define KOFF  512               // D_Q
#define VOFF  1024              // D_Q + D_K
#define QKVN  5120              // 512+512+4096
#define DVH   512               // per-head value dim (= D_IN)
#define DEXP  2048

// ---------------- scratch (device globals) ----------------
__device__ float g_xn [NTOK * (long)DIN];
__device__ float g_qkv[NTOK * (long)QKVN];
__device__ float g_S  [(long)NB*NH*SEQ*SEQ];
__device__ float g_ao [NTOK * (long)(NH*DVH)];
__device__ float g_x2 [NTOK * (long)DIN];
__device__ float g_x2n[NTOK * (long)DIN];
__device__ float g_h  [NTOK * (long)DEXP];

// ---------------- helpers ----------------
__device__ __forceinline__ uint32_t smem_u32(const void* p) {
    uint32_t a;
    asm("{ .reg .u64 t; cvta.to.shared.u64 t, %1; cvt.u32.u64 %0, t; }" : "=r"(a) : "l"(p));
    return a;
}
__device__ __forceinline__ void ldx4(uint32_t* r, uint32_t a) {
    asm volatile("ldmatrix.sync.aligned.m8n8.x4.shared.b16 {%0,%1,%2,%3}, [%4];"
                 : "=r"(r[0]), "=r"(r[1]), "=r"(r[2]), "=r"(r[3]) : "r"(a));
}
__device__ __forceinline__ void ldx4t(uint32_t* r, uint32_t a) {
    asm volatile("ldmatrix.sync.aligned.m8n8.x4.trans.shared.b16 {%0,%1,%2,%3}, [%4];"
                 : "=r"(r[0]), "=r"(r[1]), "=r"(r[2]), "=r"(r[3]) : "r"(a));
}
__device__ __forceinline__ void mma16816(float* d, const uint32_t* a, const uint32_t* b) {
    asm volatile("mma.sync.aligned.m16n8k16.row.col.f32.bf16.bf16.f32 "
                 "{%0,%1,%2,%3}, {%4,%5,%6,%7}, {%8,%9}, {%0,%1,%2,%3};"
                 : "+f"(d[0]), "+f"(d[1]), "+f"(d[2]), "+f"(d[3])
                 : "r"(a[0]), "r"(a[1]), "r"(a[2]), "r"(a[3]), "r"(b[0]), "r"(b[1]));
}
__device__ __forceinline__ void sts16(uint32_t addr, uint4 v) {
    asm volatile("st.shared.v4.b32 [%0], {%1,%2,%3,%4};"
                 :: "r"(addr), "r"(v.x), "r"(v.y), "r"(v.z), "r"(v.w) : "memory");
}
// split 8 fp32 into hi/lo bf16x2 packs
__device__ __forceinline__ void split8(const float* f, uint4& h, uint4& l) {
    uint32_t hu[4], lu[4];
    #pragma unroll
    for (int j = 0; j < 4; j++) {
        __nv_bfloat162 hb = __float22bfloat162_rn(make_float2(f[2*j], f[2*j+1]));
        uint32_t u = *(uint32_t*)&hb;
        float h0 = __uint_as_float(u << 16);
        float h1 = __uint_as_float(u & 0xFFFF0000u);
        __nv_bfloat162 lb = __float22bfloat162_rn(make_float2(f[2*j] - h0, f[2*j+1] - h1));
        hu[j] = u;
        lu[j] = *(uint32_t*)&lb;
    }
    h = make_uint4(hu[0], hu[1], hu[2], hu[3]);
    l = make_uint4(lu[0], lu[1], lu[2], lu[3]);
}

// ---------------- LayerNorm ----------------
__global__ void ln_kernel(const float* __restrict__ x, const float* __restrict__ g,
                          const float* __restrict__ bta, float* __restrict__ o) {
    __shared__ float red[2][4];
    long row = blockIdx.x;
    const float* xr = x + row * DIN;
    float* orow = o + row * DIN;
    int t = threadIdx.x;
    float4 v = ((const float4*)xr)[t];
    float s  = v.x + v.y + v.z + v.w;
    float ss = v.x*v.x + v.y*v.y + v.z*v.z + v.w*v.w;
    #pragma unroll
    for (int off = 16; off > 0; off >>= 1) {
        s  += __shfl_down_sync(0xffffffffu, s,  off);
        ss += __shfl_down_sync(0xffffffffu, ss, off);
    }
    int warp = t >> 5, lane = t & 31;
    if (lane == 0) { red[0][warp] = s; red[1][warp] = ss; }
    __syncthreads();
    if (t == 0) {
        float S0 = red[0][0] + red[0][1] + red[0][2] + red[0][3];
        float S1 = red[1][0] + red[1][1] + red[1][2] + red[1][3];
        float mu  = S0 * (1.0f/DIN);
        float var = S1 * (1.0f/DIN) - mu*mu;
        red[0][0] = mu;
        red[1][0] = rsqrtf(var + 1e-5f);
    }
    __syncthreads();
    float mu = red[0][0], inv = red[1][0];
    float4 gg = ((const float4*)g)[t];
    float4 bb = ((const float4*)bta)[t];
    float4 r;
    r.x = (v.x - mu) * inv * gg.x + bb.x;
    r.y = (v.y - mu) * inv * gg.y + bb.y;
    r.z = (v.z - mu) * inv * gg.z + bb.z;
    r.w = (v.w - mu) * inv * gg.w + bb.w;
    ((float4*)orow)[t] = r;
}

// ---------------- row softmax over 2048 ----------------
__global__ void softmax_kernel(float* __restrict__ S) {
    __shared__ float red[8];
    long row = blockIdx.x;
    float* r = S + row * (long)SEQ;
    int t = threadIdx.x;
    float4 a = ((float4*)r)[t];
    float4 b = ((float4*)r)[t + 256];
    float m = fmaxf(fmaxf(fmaxf(a.x,a.y),fmaxf(a.z,a.w)),
                    fmaxf(fmaxf(b.x,b.y),fmaxf(b.z,b.w)));
    #pragma unroll
    for (int off = 16; off > 0; off >>= 1)
        m = fmaxf(m, __shfl_xor_sync(0xffffffffu, m, off));
    int warp = t >> 5, lane = t & 31;
    if (lane == 0) red[warp] = m;
    __syncthreads();
    m = red[0];
    #pragma unroll
    for (int i = 1; i < 8; i++) m = fmaxf(m, red[i]);
    a.x = __expf(a.x - m); a.y = __expf(a.y - m); a.z = __expf(a.z - m); a.w = __expf(a.w - m);
    b.x = __expf(b.x - m); b.y = __expf(b.y - m); b.z = __expf(b.z - m); b.w = __expf(b.w - m);
    float s = a.x+a.y+a.z+a.w + b.x+b.y+b.z+b.w;
    #pragma unroll
    for (int off = 16; off > 0; off >>= 1)
        s += __shfl_xor_sync(0xffffffffu, s, off);
    __syncthreads();
    if (lane == 0) red[warp] = s;
    __syncthreads();
    s = red[0];
    #pragma unroll
    for (int i = 1; i < 8; i++) s += red[i];
    float inv = 1.0f / s;
    a.x *= inv; a.y *= inv; a.z *= inv; a.w *= inv;
    b.x *= inv; b.y *= inv; b.z *= inv; b.w *= inv;
    ((float4*)r)[t]       = a;
    ((float4*)r)[t + 256] = b;
}

// ---------------- HMMA split-bf16 GEMM ----------------
// C[M,N] = alpha * A[M,K] @ B  [+bias][+res][swish]
// BLAYOUT 0: B stored [N,K] (k contiguous). BLAYOUT 1: B stored [K,N] (n contiguous).
// CTA 128x128, 8 warps (2x4), warp tile 64x32, BK=32, double buffered.
// SMEM per stage: A hi/lo [128][40] bf16 (10240 B each),
//   B(NK) hi/lo [128][40] (10240 B each) or B(KN) hi/lo [32][136] (8704 B each).
#define STAGE_B  40960
#define SMEM_SZ  (2 * STAGE_B)   // 81920

template<int BLAYOUT, bool BIAS, bool RES, bool SWISH>
__global__ void __launch_bounds__(256, 1)
hmma_gemm(const float* __restrict__ A, const float* __restrict__ B, float* __restrict__ C,
          const float* __restrict__ bias, const float* __restrict__ res,
          int K, int lda, int ldb, int ldc,
          long sA1, long sA2, long sB1, long sB2, long sC1, long sC2,
          int zdiv, float alpha)
{
    extern __shared__ char sm[];
    const uint32_t smb = smem_u32(sm);
    const int tid = threadIdx.x, wid = tid >> 5, lane = tid & 31;
    const int wm = wid & 1, wn = wid >> 1;

    int z = blockIdx.z, z1 = z / zdiv, z2 = z - z1 * zdiv;
    A += z1 * sA1 + (long)z2 * sA2;
    B += z1 * sB1 + (long)z2 * sB2;
    C += z1 * sC1 + (long)z2 * sC2;
    const long bm0 = (long)blockIdx.y * 128;
    const long bn0 = (long)blockIdx.x * 128;

    // loader indices
    const int mA = tid >> 1, kA = (tid & 1) << 4;          // A: [m][k], 16 k per thread
    const int rB = (BLAYOUT == 0) ? (tid >> 1) : (tid >> 3);
    const int cB = (BLAYOUT == 0) ? ((tid & 1) << 4) : ((tid & 7) << 4);
    const int BSZ = (BLAYOUT == 0) ? 10240 : 8704;

    float acc[4][4][4];
    #pragma unroll
    for (int i = 0; i < 4; i++)
        #pragma unroll
        for (int j = 0; j < 4; j++)
            #pragma unroll
            for (int t = 0; t < 4; t++) acc[i][j][t] = 0.0f;

    float4 fa[4], fb[4];
    auto gload = [&](int k0) {
        const float* Ap = A + (bm0 + mA) * (long)lda + k0 + kA;
        #pragma unroll
        for (int i = 0; i < 4; i++) fa[i] = *(const float4*)(Ap + i * 4);
        const float* Bp = (BLAYOUT == 0)
            ? B + (bn0 + rB) * (long)ldb + k0 + cB
            : B + (long)(k0 + rB) * ldb + bn0 + cB;
        #pragma unroll
        for (int i = 0; i < 4; i++) fb[i] = *(const float4*)(Bp + i * 4);
    };

    auto sstore = [&](int buf) {
        const uint32_t base = smb + buf * STAGE_B;
        // A
        {
            uint4 h, l;
            uint32_t off = base + mA * 80 + kA * 2;
            split8((const float*)&fa[0], h, l);
            sts16(off, h);           sts16(off + 10240, l);
            split8((const float*)&fa[2], h, l);
            sts16(off + 16, h);      sts16(off + 10240 + 16, l);
        }
        // B
        {
            uint4 h, l;
            uint32_t off = base + 20480 +
                ((BLAYOUT == 0) ? (rB * 80 + cB * 2) : (rB * 272 + cB * 2));
            split8((const float*)&fb[0], h, l);
            sts16(off, h);           sts16(off + BSZ, l);
            split8((const float*)&fb[2], h, l);
            sts16(off + 16, h);      sts16(off + BSZ + 16, l);
        }
    };

    auto mma_chunk = [&](int buf) {
        const uint32_t base = smb + buf * STAGE_B;
        #pragma unroll
        for (int ks = 0; ks < 2; ks++) {
            const int kk = ks * 16;
            uint32_t ah[4][4], al[4][4];
            #pragma unroll
            for (int mi = 0; mi < 4; mi++) {
                uint32_t ad = base + (wm * 64 + mi * 16 + (lane & 15)) * 80
                                   + (kk + (lane >> 4) * 8) * 2;
                ldx4(ah[mi], ad);
                ldx4(al[mi], ad + 10240);
            }
            uint32_t bh[4][2], bl[4][2];
            if (BLAYOUT == 0) {
                #pragma unroll
                for (int p = 0; p < 2; p++) {
                    uint32_t bd = base + 20480 + (wn * 32 + p * 16 + (lane & 15)) * 80
                                       + (kk + (lane >> 4) * 8) * 2;
                    uint32_t r[4];
                    ldx4(r, bd);
                    bh[2*p][0] = r[0]; bh[2*p][1] = r[2];
                    bh[2*p+1][0] = r[1]; bh[2*p+1][1] = r[3];
                    ldx4(r, bd + BSZ);
                    bl[2*p][0] = r[0]; bl[2*p][1] = r[2];
                    bl[2*p+1][0] = r[1]; bl[2*p+1][1] = r[3];
                }
            } else {
                #pragma unroll
                for (int p = 0; p < 2; p++) {
                    int row = kk + (lane & 7) + ((lane >> 3) & 1) * 8;
                    int col = wn * 32 + p * 16 + (lane >> 4) * 8;
                    uint32_t bd = base + 20480 + row * 272 + col * 2;
                    uint32_t r[4];
                    ldx4t(r, bd);
                    bh[2*p][0] = r[0]; bh[2*p][1] = r[1];
                    bh[2*p+1][0] = r[2]; bh[2*p+1][1] = r[3];
                    ldx4t(r, bd + BSZ);
                    bl[2*p][0] = r[0]; bl[2*p][1] = r[1];
                    bl[2*p+1][0] = r[2]; bl[2*p+1][1] = r[3];
                }
            }
            #pragma unroll
            for (int mi = 0; mi < 4; mi++)
                #pragma unroll
                for (int ni = 0; ni < 4; ni++) {
                    mma16816(acc[mi][ni], ah[mi], bh[ni]);
                    mma16816(acc[mi][ni], ah[mi], bl[ni]);
                    mma16816(acc[mi][ni], al[mi], bh[ni]);
                }
        }
    };

    const int chunks = K >> 5;
    gload(0);
    sstore(0);
    __syncthreads();
    for (int c = 0; c < chunks; c++) {
        if (c + 1 < chunks) gload((c + 1) << 5);
        mma_chunk(c & 1);
        __syncthreads();
        if (c + 1 < chunks) {
            sstore((c + 1) & 1);
            __syncthreads();
        }
    }

    // epilogue
    #pragma unroll
    for (int mi = 0; mi < 4; mi++) {
        #pragma unroll
        for (int ni = 0; ni < 4; ni++) {
            long n = bn0 + wn * 32 + ni * 8 + (lane & 3) * 2;
            #pragma unroll
            for (int half = 0; half < 2; half++) {
                long m = bm0 + wm * 64 + mi * 16 + (lane >> 2) + half * 8;
                float2 v;
                v.x = acc[mi][ni][half * 2 + 0] * alpha;
                v.y = acc[mi][ni][half * 2 + 1] * alpha;
                if (BIAS) {
                    float2 bb = *(const float2*)(bias + n);
                    v.x += bb.x; v.y += bb.y;
                }
                if (SWISH) {
                    v.x = v.x / (1.0f + __expf(-v.x));
                    v.y = v.y / (1.0f + __expf(-v.y));
                }
                if (RES) {
                    float2 rr = *(const float2*)(res + m * (long)ldc + n);
                    v.x += rr.x; v.y += rr.y;
                }
                *(float2*)(C + m * (long)ldc + n) = v;
            }
        }
    }
}

// ---------------- host orchestration ----------------
extern "C" void kernel_launch(void* const* d_in, const int* in_sizes, int n_in,
                              void* d_out, int out_size) {
    const float* x     = (const float*)d_in[0];
    const float* ln1_g = (const float*)d_in[1];
    const float* ln1_b = (const float*)d_in[2];
    const float* Wqkv  = (const float*)d_in[3];
    const float* bqkv  = (const float*)d_in[4];
    const float* Wm    = (const float*)d_in[5];
    const float* bm    = (const float*)d_in[6];
    const float* ln2_g = (const float*)d_in[7];
    const float* ln2_b = (const float*)d_in[8];
    const float* W1    = (const float*)d_in[9];
    const float* b1    = (const float*)d_in[10];
    const float* W2    = (const float*)d_in[11];
    const float* b2    = (const float*)d_in[12];
    float* out = (float*)d_out;

    float *xn, *qkv, *S, *ao, *x2, *x2n, *h;
    cudaGetSymbolAddress((void**)&xn,  g_xn);
    cudaGetSymbolAddress((void**)&qkv, g_qkv);
    cudaGetSymbolAddress((void**)&S,   g_S);
    cudaGetSymbolAddress((void**)&ao,  g_ao);
    cudaGetSymbolAddress((void**)&x2,  g_x2);
    cudaGetSymbolAddress((void**)&x2n, g_x2n);
    cudaGetSymbolAddress((void**)&h,   g_h);

    cudaFuncSetAttribute(hmma_gemm<1, true,  false, false>, cudaFuncAttributeMaxDynamicSharedMemorySize, SMEM_SZ);
    cudaFuncSetAttribute(hmma_gemm<0, false, false, false>, cudaFuncAttributeMaxDynamicSharedMemorySize, SMEM_SZ);
    cudaFuncSetAttribute(hmma_gemm<1, false, false, false>, cudaFuncAttributeMaxDynamicSharedMemorySize, SMEM_SZ);
    cudaFuncSetAttribute(hmma_gemm<1, true,  true,  false>, cudaFuncAttributeMaxDynamicSharedMemorySize, SMEM_SZ);
    cudaFuncSetAttribute(hmma_gemm<1, true,  false, true >, cudaFuncAttributeMaxDynamicSharedMemorySize, SMEM_SZ);

    const float scale = 0.125f;  // 1/sqrt(64)

    // 1) LN1
    ln_kernel<<<NTOK, 128>>>(x, ln1_g, ln1_b, xn);

    // 2) qkv = xn @ Wqkv + bqkv            (4096 x 5120, K=512), B=[K,N]
    hmma_gemm<1, true, false, false><<<dim3(QKVN/128, NTOK/128, 1), 256, SMEM_SZ>>>(
        xn, Wqkv, qkv, bqkv, nullptr,
        DIN, DIN, QKVN, QKVN,
        0, 0, 0, 0, 0, 0, 1, 1.0f);

    // 3) S[b,h] = scale * Q[b,h] @ K[b,h]^T   (2048x2048, K=64), B=[N,K], 16 batches
    hmma_gemm<0, false, false, false><<<dim3(SEQ/128, SEQ/128, NB*NH), 256, SMEM_SZ>>>(
        qkv + QOFF, qkv + KOFF, S, nullptr, nullptr,
        DH, QKVN, QKVN, SEQ,
        (long)SEQ*QKVN, DH,
        (long)SEQ*QKVN, DH,
        (long)NH*SEQ*SEQ, (long)SEQ*SEQ,
        NH, scale);

    // 4) softmax rows of S
    softmax_kernel<<<NB*NH*SEQ, 256>>>(S);

    // 5) ao = P[b,h] @ V[b,h]               (2048 x 512, K=2048), B=[K,N], 16 batches
    hmma_gemm<1, false, false, false><<<dim3(DVH/128, SEQ/128, NB*NH), 256, SMEM_SZ>>>(
        S, qkv + VOFF, ao, nullptr, nullptr,
        SEQ, SEQ, QKVN, NH*DVH,
        (long)NH*SEQ*SEQ, (long)SEQ*SEQ,
        (long)SEQ*QKVN, DVH,
        (long)SEQ*NH*DVH, DVH,
        NH, 1.0f);

    // 6) x2 = ao @ Wm + bm + x              (4096 x 512, K=4096), B=[K,N]
    hmma_gemm<1, true, true, false><<<dim3(DIN/128, NTOK/128, 1), 256, SMEM_SZ>>>(
        ao, Wm, x2, bm, x,
        NH*DVH, NH*DVH, DIN, DIN,
        0, 0, 0, 0, 0, 0, 1, 1.0f);

    // 7) LN2
    ln_kernel<<<NTOK, 128>>>(x2, ln2_g, ln2_b, x2n);

    // 8) h = swish(x2n @ W1 + b1)           (4096 x 2048, K=512), B=[K,N]
    hmma_gemm<1, true, false, true><<<dim3(DEXP/128, NTOK/128, 1), 256, SMEM_SZ>>>(
        x2n, W1, h, b1, nullptr,
        DIN, DIN, DEXP, DEXP,
        0, 0, 0, 0, 0, 0, 1, 1.0f);

    // 9) out = h @ W2 + b2 + x2             (4096 x 512, K=2048), B=[K,N]
    hmma_gemm<1, true, true, false><<<dim3(DIN/128, NTOK/128, 1), 256, SMEM_SZ>>>(
        h, W2, out, b2, x2,
        DEXP, DEXP, DIN, DIN,
        0, 0, 0, 0, 0, 0, 1, 1.0f);
}